// round 9
// baseline (speedup 1.0000x reference)
#include <cuda_runtime.h>
#include <cuda_bf16.h>
#include <math.h>
#include <stdint.h>

#define N_SEQ 4096
#define N_HEADS 16
#define DIM_HEAD 64
#define DIM 1024
#define CMAX 18.5f

// ---------------- scratch (device globals; no allocation allowed) ----------
// q/k after rope+l2norm+qk_scale (+0.125*log2e folded into q), stored as
// packed bf16 pairs: hi = bf16(x), lo = bf16(x - hi). Word w holds dims
// (2w, 2w+1) of a 64-dim head row. Layout [h][n][32 words].
__device__ uint32_t g_qhib[N_HEADS * N_SEQ * 32];
__device__ uint32_t g_qlob[N_HEADS * N_SEQ * 32];
__device__ uint32_t g_khib[N_HEADS * N_SEQ * 32];
__device__ uint32_t g_klob[N_HEADS * N_SEQ * 32];
// v as tf32-rna PAIRS for the m16n8k8 B-fragment: g_vp[h][pair][d] where
// pair p = tile*32 + ks*4 + c holds {V[key=tile*64+ks*8+c][d], V[key+4][d]}.
__device__ float2 g_vp[N_HEADS * 2048 * 64];
__device__ float g_wr [DIM * DIM];                   // w_out, tf32-rna, natural [j][i]
__device__ float g_attn[N_SEQ * DIM];                // attention out, tf32-rna, [n][dim]
__device__ float g_cos[N_SEQ * 32];
__device__ float g_sin[N_SEQ * 32];

// ---------------- helpers ---------------------------------------------------
__device__ __forceinline__ uint32_t smem_u32(const void* p) {
    uint32_t a;
    asm("{ .reg .u64 t; cvta.to.shared.u64 t, %1; cvt.u32.u64 %0, t; }" : "=r"(a) : "l"(p));
    return a;
}
__device__ __forceinline__ float tf32_rna(float x) {
    uint32_t r;
    asm("cvt.rna.tf32.f32 %0, %1;" : "=r"(r) : "f"(x));
    return __uint_as_float(r);
}
__device__ __forceinline__ uint32_t packbf(float a, float b) {
    __nv_bfloat162 t = __floats2bfloat162_rn(a, b);   // a -> low half (dim 2l)
    return *(uint32_t*)&t;
}
// tf32 m16n8k8 (PV + projection)
__device__ __forceinline__ void mma8(float* c,
    uint32_t a0, uint32_t a1, uint32_t a2, uint32_t a3,
    uint32_t b0, uint32_t b1)
{
    asm volatile(
        "mma.sync.aligned.m16n8k8.row.col.f32.tf32.tf32.f32 "
        "{%0,%1,%2,%3}, {%4,%5,%6,%7}, {%8,%9}, {%0,%1,%2,%3};"
        : "+f"(c[0]), "+f"(c[1]), "+f"(c[2]), "+f"(c[3])
        : "r"(a0), "r"(a1), "r"(a2), "r"(a3), "r"(b0), "r"(b1));
}
// bf16 m16n8k16 (QK hi/lo passes)
__device__ __forceinline__ void mma16(float* c, const uint32_t* a,
                                      uint32_t b0, uint32_t b1)
{
    asm volatile(
        "mma.sync.aligned.m16n8k16.row.col.f32.bf16.bf16.f32 "
        "{%0,%1,%2,%3}, {%4,%5,%6,%7}, {%8,%9}, {%0,%1,%2,%3};"
        : "+f"(c[0]), "+f"(c[1]), "+f"(c[2]), "+f"(c[3])
        : "r"(a[0]), "r"(a[1]), "r"(a[2]), "r"(a[3]), "r"(b0), "r"(b1));
}
// ldmatrix x4: 4 8x8 b16 matrices; lane l supplies row (l&7) of matrix (l>>3);
// result reg i = matrix i, thread holds word (row=lane>>2, wordcol=lane&3).
#define LDSM4(r, a) \
    asm volatile("ldmatrix.sync.aligned.m8n8.x4.shared.b16 {%0,%1,%2,%3}, [%4];" \
        : "=r"((r)[0]), "=r"((r)[1]), "=r"((r)[2]), "=r"((r)[3]) : "r"(a))
__device__ __forceinline__ void cp16(uint32_t dst, const void* src) {
    asm volatile("cp.async.cg.shared.global [%0], [%1], 16;" :: "r"(dst), "l"(src));
}
#define CP_COMMIT() asm volatile("cp.async.commit_group;" ::: "memory")
#define CP_WAIT1()  asm volatile("cp.async.wait_group 1;" ::: "memory")
#define CP_WAIT0()  asm volatile("cp.async.wait_group 0;" ::: "memory")

// ---------------------------------------------------------------------------
// Kernel 0: RoPE tables (double sincos of the fp32-rounded angle)
// ---------------------------------------------------------------------------
__global__ void rope_table_kernel() {
    int idx = blockIdx.x * blockDim.x + threadIdx.x;
    if (idx >= N_SEQ * 32) return;
    int n = idx >> 5, l = idx & 31;
    float invf = (float)exp(-((double)l / 32.0) * log(10000.0));
    float ang = (float)n * invf;
    double s, c;
    sincos((double)ang, &s, &c);
    g_cos[idx] = (float)c;
    g_sin[idx] = (float)s;
}

// ---------------------------------------------------------------------------
// Kernel 1: prep q/k: RoPE + l2norm + qk_scale (+0.125*log2e into q),
// bf16 hi/lo split, packed-pair layout [h][n][32w]. One warp per (token, head).
// ---------------------------------------------------------------------------
__global__ __launch_bounds__(256) void prep_qk_kernel(
    const float* __restrict__ q, const float* __restrict__ k,
    const float* __restrict__ qk_scale)
{
    int wi = blockIdx.x * 8 + (threadIdx.x >> 5);   // 0..65535
    int l = threadIdx.x & 31;
    int h = wi & 15;
    int n = wi >> 4;
    const float* src = (blockIdx.y == 0) ? q : k;
    uint32_t* dhi = (blockIdx.y == 0) ? g_qhib : g_khib;
    uint32_t* dlo = (blockIdx.y == 0) ? g_qlob : g_klob;
    float fold = (blockIdx.y == 0) ? (0.125f * 1.4426950408889634f) : 1.0f;

    float2 x = ((const float2*)(src + (size_t)n * DIM + h * DIM_HEAD))[l];
    float2 sc = ((const float2*)qk_scale)[l];
    float c = g_cos[n * 32 + l], s = g_sin[n * 32 + l];
    float orr = x.x * c - x.y * s;
    float oii = x.x * s + x.y * c;
    float sq = orr * orr + oii * oii;
    #pragma unroll
    for (int m = 16; m; m >>= 1) sq += __shfl_xor_sync(0xffffffffu, sq, m);
    float f = fold / fmaxf(sqrtf(sq), 1e-12f);
    float a = orr * f * sc.x;
    float b = oii * f * sc.y;
    float ah = __bfloat162float(__float2bfloat16(a));
    float bh = __bfloat162float(__float2bfloat16(b));
    size_t o = ((size_t)h * N_SEQ + n) * 32 + l;
    dhi[o] = packbf(a, b);            // rn re-round == (ah, bh)
    dlo[o] = packbf(a - ah, b - bh);
}

// ---------------------------------------------------------------------------
// Kernel 2a: v -> paired tf32 layout g_vp (replaces vround)
// thread: one (h, pair, 4-dim chunk): reads 16B from key and key+4 rows.
// ---------------------------------------------------------------------------
__global__ __launch_bounds__(256) void vpair_kernel(const float* __restrict__ v) {
    int id = blockIdx.x * 256 + threadIdx.x;       // 0 .. 524287
    int h = id >> 15;
    int rem = id & 32767;
    int p = rem >> 4;                               // 0..2047
    int chunk = rem & 15;
    int t = p >> 5, w = p & 31;
    int key0 = t * 64 + (w >> 2) * 8 + (w & 3);
    float4 a = *(const float4*)(v + (size_t)key0 * DIM + h * 64 + chunk * 4);
    float4 b = *(const float4*)(v + (size_t)(key0 + 4) * DIM + h * 64 + chunk * 4);
    float2* dst = g_vp + (((size_t)h * 2048 + p) * 64 + chunk * 4);
    dst[0] = make_float2(tf32_rna(a.x), tf32_rna(b.x));
    dst[1] = make_float2(tf32_rna(a.y), tf32_rna(b.y));
    dst[2] = make_float2(tf32_rna(a.z), tf32_rna(b.z));
    dst[3] = make_float2(tf32_rna(a.w), tf32_rna(b.w));
}

// ---------------------------------------------------------------------------
// Kernel 2b: elementwise rna rounding of w_out (tf32 operand for proj)
// ---------------------------------------------------------------------------
__global__ __launch_bounds__(256) void wround_kernel(const float* __restrict__ w) {
    int i = blockIdx.x * 256 + threadIdx.x;
    float4 x = ((const float4*)w)[i];
    ((float4*)g_wr)[i] = make_float4(tf32_rna(x.x), tf32_rna(x.y), tf32_rna(x.z), tf32_rna(x.w));
}

// ---------------------------------------------------------------------------
// Kernel 3: flash attention. CTA = 128 q-rows x 1 head; 8 warps x 16 rows;
// 64 KV tiles of 64 keys, double-buffered via cp.async.
// S = 2xbf16 (hi*hi + hi*lo + lo*hi) on m16n8k16, K B-frags via ldmatrix.x4;
// PV = tf32 m16n8k8 with paired-V LDS.64 B-frags. Fixed-max softmax.
// SMEM per buffer: Khi 64x36w (9216B), Klo (+9216), Vp 32x68 float2
// (+18432, 17408B) => 35840B/buf, 71680B total.
// ---------------------------------------------------------------------------
#define KV_STR_B 35840
#define ATTN_SMEM_BYTES (2 * KV_STR_B)

__device__ __forceinline__ void issue_kv(uint32_t base, int h, int k0, int tid)
{
    #pragma unroll
    for (int j = 0; j < 2; j++) {
        int id = tid + j * 256;       // 0..511
        int row = id >> 3;            // 0..63
        int ch = id & 7;              // 16B chunk
        const uint32_t* skh = g_khib + ((size_t)h * N_SEQ + k0 + row) * 32 + ch * 4;
        const uint32_t* skl = g_klob + ((size_t)h * N_SEQ + k0 + row) * 32 + ch * 4;
        cp16(base + (uint32_t)(row * 144 + ch * 16), skh);
        cp16(base + (uint32_t)(9216 + row * 144 + ch * 16), skl);
    }
    int t32 = (k0 >> 6) * 32;
    #pragma unroll
    for (int j = 0; j < 4; j++) {
        int id = tid + j * 256;       // 0..1023
        int row = id >> 5;            // pair row 0..31
        int ch = id & 31;             // 16B chunk (2 float2)
        cp16(base + (uint32_t)(18432 + row * 544 + ch * 16),
             (const char*)g_vp + (((size_t)h * 2048 + t32 + row) * 64 + ch * 2) * 8);
    }
}

__global__ __launch_bounds__(256) void attn_kernel()
{
    extern __shared__ char smb[];
    uint32_t kvu0 = smem_u32(smb);

    int tid = threadIdx.x;
    int warp = tid >> 5, lane = tid & 31;
    int r = lane >> 2, c = lane & 3;
    int h = blockIdx.y, m0 = blockIdx.x * 128;

    issue_kv(kvu0, h, 0, tid);             CP_COMMIT();
    issue_kv(kvu0 + KV_STR_B, h, 64, tid); CP_COMMIT();

    // Q fragments (hi/lo), tile-invariant: 4 k16-steps x 4 regs each
    uint32_t qhf[4][4], qlf[4][4];
    {
        const uint32_t* qh = g_qhib + ((size_t)h * N_SEQ + m0 + warp * 16 + r) * 32;
        const uint32_t* ql = g_qlob + ((size_t)h * N_SEQ + m0 + warp * 16 + r) * 32;
        #pragma unroll
        for (int ks = 0; ks < 4; ks++) {
            qhf[ks][0] = qh[ks * 8 + c];
            qhf[ks][1] = qh[256 + ks * 8 + c];
            qhf[ks][2] = qh[ks * 8 + c + 4];
            qhf[ks][3] = qh[256 + ks * 8 + c + 4];
            qlf[ks][0] = ql[ks * 8 + c];
            qlf[ks][1] = ql[256 + ks * 8 + c];
            qlf[ks][2] = ql[ks * 8 + c + 4];
            qlf[ks][3] = ql[256 + ks * 8 + c + 4];
        }
    }

    float s[8][4], o[8][4];
    float lsum0 = 0.0f, lsum1 = 0.0f;
    #pragma unroll
    for (int nf = 0; nf < 8; nf++)
        #pragma unroll
        for (int e = 0; e < 4; e++) o[nf][e] = 0.0f;

    int src0 = (lane & ~3) | (c >> 1);
    int src1 = src0 + 2;
    bool odd = (c & 1) != 0;
    // ldmatrix lane address offset (within a buffer): row (lane&7), matrix (lane>>3)
    uint32_t lmoff = (uint32_t)((lane & 7) * 144 + (lane >> 3) * 32);

    for (int t = 0; t < 64; t++) {
        if (t == 63) { CP_WAIT0(); } else { CP_WAIT1(); }
        __syncthreads();
        uint32_t bufu = kvu0 + (uint32_t)(t & 1) * KV_STR_B;
        const float2* Vp = (const float2*)(smb + (t & 1) * KV_STR_B + 18432);

        #pragma unroll
        for (int nf = 0; nf < 8; nf++)
            #pragma unroll
            for (int e = 0; e < 4; e++) s[nf][e] = 0.0f;

        // ---- S = Q K^T, 2xbf16 (3 passes, k16), K frags via ldmatrix.x4 ----
        uint32_t abase = bufu + lmoff;
        #pragma unroll
        for (int nf = 0; nf < 8; nf++) {
            uint32_t bh0[4], bh1[4], bl0[4], bl1[4];
            LDSM4(bh0, abase);
            LDSM4(bh1, abase + 16);
            LDSM4(bl0, abase + 9216);
            LDSM4(bl1, abase + 9216 + 16);
            #pragma unroll
            for (int ks = 0; ks < 4; ks++) {
                mma16(s[nf], qhf[ks], bh0[ks], bh1[ks]);
                mma16(s[nf], qhf[ks], bl0[ks], bl1[ks]);
                mma16(s[nf], qlf[ks], bh0[ks], bh1[ks]);
            }
            abase += 1152;
        }

        // ---- softmax numerators (log2 units, fixed shift); rna BEFORE sum
        //      so PV numerator and denominator share the same rounding ----
        #pragma unroll
        for (int nf = 0; nf < 8; nf++) {
            s[nf][0] = tf32_rna(exp2f(s[nf][0] - CMAX));
            s[nf][1] = tf32_rna(exp2f(s[nf][1] - CMAX));
            s[nf][2] = tf32_rna(exp2f(s[nf][2] - CMAX));
            s[nf][3] = tf32_rna(exp2f(s[nf][3] - CMAX));
            lsum0 += s[nf][0] + s[nf][1];
            lsum1 += s[nf][2] + s[nf][3];
        }

        // ---- O += P V : shfl-relayout C-frags -> A-frags; paired-V LDS.64 ----
        #pragma unroll
        for (int ks = 0; ks < 8; ks++) {
            float v00 = __shfl_sync(0xffffffffu, s[ks][0], src0);
            float v01 = __shfl_sync(0xffffffffu, s[ks][1], src0);
            float v10 = __shfl_sync(0xffffffffu, s[ks][2], src0);
            float v11 = __shfl_sync(0xffffffffu, s[ks][3], src0);
            float w00 = __shfl_sync(0xffffffffu, s[ks][0], src1);
            float w01 = __shfl_sync(0xffffffffu, s[ks][1], src1);
            float w10 = __shfl_sync(0xffffffffu, s[ks][2], src1);
            float w11 = __shfl_sync(0xffffffffu, s[ks][3], src1);
            uint32_t a0 = __float_as_uint(odd ? v01 : v00);
            uint32_t a1 = __float_as_uint(odd ? v11 : v10);
            uint32_t a2 = __float_as_uint(odd ? w01 : w00);
            uint32_t a3 = __float_as_uint(odd ? w11 : w10);
            const float2* vp = Vp + (ks * 4 + c) * 68 + r;
            #pragma unroll
            for (int nf = 0; nf < 8; nf++) {
                float2 v2 = vp[nf * 8];
                mma8(o[nf], a0, a1, a2, a3,
                     __float_as_uint(v2.x), __float_as_uint(v2.y));
            }
        }

        __syncthreads();
        if (t + 2 < 64) {
            issue_kv(kvu0 + (uint32_t)(t & 1) * KV_STR_B, h, (t + 2) * 64, tid);
            CP_COMMIT();
        }
    }

    // ---- epilogue: quad row sums, normalize, rna, store ----
    lsum0 += __shfl_xor_sync(0xffffffffu, lsum0, 1);
    lsum0 += __shfl_xor_sync(0xffffffffu, lsum0, 2);
    lsum1 += __shfl_xor_sync(0xffffffffu, lsum1, 1);
    lsum1 += __shfl_xor_sync(0xffffffffu, lsum1, 2);
    float inv0 = 1.0f / lsum0, inv1 = 1.0f / lsum1;
    int row0 = m0 + warp * 16 + r;
    #pragma unroll
    for (int nf = 0; nf < 8; nf++) {
        int col = h * DIM_HEAD + nf * 8 + 2 * c;
        float2 x0 = make_float2(tf32_rna(o[nf][0] * inv0), tf32_rna(o[nf][1] * inv0));
        float2 x1 = make_float2(tf32_rna(o[nf][2] * inv1), tf32_rna(o[nf][3] * inv1));
        *(float2*)&g_attn[(size_t)row0 * DIM + col] = x0;
        *(float2*)&g_attn[(size_t)(row0 + 8) * DIM + col] = x1;
    }
}

// ---------------------------------------------------------------------------
// Kernel 4: projection GEMM on mma.sync tf32 (unchanged, validated R5/R8).
// out[n][j] = sum_i attn[n][i] * w[j][i] + b[j]. CTA 128x128, warps 4x2.
// ---------------------------------------------------------------------------
#define PROJ_STRF 17408
#define PROJ_SMEM_BYTES (2 * PROJ_STRF * 4)

__device__ __forceinline__ void issue_proj(uint32_t base, int m0, int j0, int k0, int tid)
{
    #pragma unroll
    for (int j = 0; j < 8; j++) {
        int id = tid + j * 256;
        int row = id >> 4;
        int c4 = (id & 15) * 4;
        cp16(base + (uint32_t)(row * 68 + c4) * 4u,
             g_attn + (size_t)(m0 + row) * DIM + k0 + c4);
        cp16(base + (uint32_t)(8704 + row * 68 + c4) * 4u,
             g_wr + (size_t)(j0 + row) * DIM + k0 + c4);
    }
}

__global__ __launch_bounds__(256) void proj_kernel(
    const float* __restrict__ b_out, float* __restrict__ out)
{
    extern __shared__ float sm[];
    uint32_t smu = smem_u32(sm);
    int tid = threadIdx.x;
    int warp = tid >> 5, lane = tid & 31;
    int r = lane >> 2, c = lane & 3;
    int mw = warp >> 1, nw = warp & 1;
    int m0 = blockIdx.x * 128, j0 = blockIdx.y * 128;

    float acc[2][8][4];
    #pragma unroll
    for (int mf = 0; mf < 2; mf++)
        #pragma unroll
        for (int nf = 0; nf < 8; nf++)
            #pragma unroll
            for (int e = 0; e < 4; e++) acc[mf][nf][e] = 0.0f;

    issue_proj(smu, m0, j0, 0, tid);                    CP_COMMIT();
    issue_proj(smu + PROJ_STRF * 4u, m0, j0, 64, tid);  CP_COMMIT();

    for (int ch = 0; ch < 16; ch++) {
        if (ch == 15) { CP_WAIT0(); } else { CP_WAIT1(); }
        __syncthreads();
        float* As = sm + (ch & 1) * PROJ_STRF;
        float* Ws = As + 8704;

        #pragma unroll
        for (int ks = 0; ks < 8; ks++) {
            int k0 = ks * 8;
            uint32_t a[2][4];
            #pragma unroll
            for (int mf = 0; mf < 2; mf++) {
                const float* ab = &As[(mw * 32 + mf * 16 + r) * 68 + k0 + c];
                a[mf][0] = __float_as_uint(ab[0]);
                a[mf][1] = __float_as_uint(ab[8 * 68]);
                a[mf][2] = __float_as_uint(ab[4]);
                a[mf][3] = __float_as_uint(ab[8 * 68 + 4]);
            }
            #pragma unroll
            for (int nf = 0; nf < 8; nf++) {
                const float* wb = &Ws[(nw * 64 + nf * 8 + r) * 68 + k0 + c];
                uint32_t b0 = __float_as_uint(wb[0]);
                uint32_t b1 = __float_as_uint(wb[4]);
                mma8(acc[0][nf], a[0][0], a[0][1], a[0][2], a[0][3], b0, b1);
                mma8(acc[1][nf], a[1][0], a[1][1], a[1][2], a[1][3], b0, b1);
            }
        }

        __syncthreads();
        if (ch + 2 < 16) {
            issue_proj(smu + (uint32_t)(ch & 1) * PROJ_STRF * 4u, m0, j0, (ch + 2) * 64, tid);
            CP_COMMIT();
        }
    }

    #pragma unroll
    for (int mf = 0; mf < 2; mf++) {
        int row = m0 + mw * 32 + mf * 16 + r;
        #pragma unroll
        for (int nf = 0; nf < 8; nf++) {
            int col = j0 + nw * 64 + nf * 8 + 2 * c;
            float2 bb = *(const float2*)&b_out[col];
            *(float2*)&out[(size_t)row * DIM + col] =
                make_float2(acc[mf][nf][0] + bb.x, acc[mf][nf][1] + bb.y);
            *(float2*)&out[(size_t)(row + 8) * DIM + col] =
                make_float2(acc[mf][nf][2] + bb.x, acc[mf][nf][3] + bb.y);
        }
    }
}

// ---------------------------------------------------------------------------
extern "C" void kernel_launch(void* const* d_in, const int* in_sizes, int n_in,
                              void* d_out, int out_size)
{
    const float* q        = (const float*)d_in[0];
    const float* k        = (const float*)d_in[1];
    const float* v        = (const float*)d_in[2];
    const float* qk_scale = (const float*)d_in[3];
    const float* w_out    = (const float*)d_in[4];
    const float* b_out    = (const float*)d_in[5];
    float* out = (float*)d_out;

    cudaFuncSetAttribute(attn_kernel,
                         cudaFuncAttributeMaxDynamicSharedMemorySize, ATTN_SMEM_BYTES);
    cudaFuncSetAttribute(proj_kernel,
                         cudaFuncAttributeMaxDynamicSharedMemorySize, PROJ_SMEM_BYTES);

    rope_table_kernel<<<(N_SEQ * 32 + 255) / 256, 256>>>();
    prep_qk_kernel<<<dim3(8192, 2), 256>>>(q, k, qk_scale);
    vpair_kernel<<<2048, 256>>>(v);
    wround_kernel<<<(DIM * DIM / 4) / 256, 256>>>(w_out);
    attn_kernel<<<dim3(N_SEQ / 128, N_HEADS), 256, ATTN_SMEM_BYTES>>>();
    proj_kernel<<<dim3(N_SEQ / 128, DIM / 128), 256, PROJ_SMEM_BYTES>>>(b_out, out);
}

// round 14
// speedup vs baseline: 2.0401x; 2.0401x over previous
#include <cuda_runtime.h>
#include <cuda_bf16.h>
#include <cuda_fp16.h>
#include <math.h>
#include <stdint.h>

#define N_SEQ 4096
#define N_HEADS 16
#define DIM_HEAD 64
#define DIM 1024
#define CMAX 18.5f

// ---------------- scratch (device globals; no allocation allowed) ----------
// q/k after rope+l2norm+qk_scale (+0.125*log2e folded into q), packed fp16
// pairs: word w = dims (2w, 2w+1). Layout [h][n][32 words].
__device__ uint32_t g_qf[N_HEADS * N_SEQ * 32];
__device__ uint32_t g_kf[N_HEADS * N_SEQ * 32];
// v as fp16 KEY-PAIR words for the m16n8k16 B-fragment:
// g_vph[h][kp][d] = {V[2kp][d] (lo), V[2kp+1][d] (hi)}, kp = 0..2047, d = 0..63
__device__ uint32_t g_vph[N_HEADS * 2048 * 64];
__device__ float g_wr [DIM * DIM];                   // w_out, tf32-rna, natural [j][i]
__device__ float g_attn[N_SEQ * DIM];                // attention out, tf32-rna, [n][dim]
__device__ float g_cos[N_SEQ * 32];
__device__ float g_sin[N_SEQ * 32];

// ---------------- helpers ---------------------------------------------------
__device__ __forceinline__ uint32_t smem_u32(const void* p) {
    uint32_t a;
    asm("{ .reg .u64 t; cvta.to.shared.u64 t, %1; cvt.u32.u64 %0, t; }" : "=r"(a) : "l"(p));
    return a;
}
__device__ __forceinline__ float tf32_rna(float x) {
    uint32_t r;
    asm("cvt.rna.tf32.f32 %0, %1;" : "=r"(r) : "f"(x));
    return __uint_as_float(r);
}
__device__ __forceinline__ uint32_t packh2(float a, float b) {
    __half2 t = __floats2half2_rn(a, b);   // a -> low half (lower index)
    return *(uint32_t*)&t;
}
// tf32 m16n8k8 (projection)
__device__ __forceinline__ void mma8(float* c,
    uint32_t a0, uint32_t a1, uint32_t a2, uint32_t a3,
    uint32_t b0, uint32_t b1)
{
    asm volatile(
        "mma.sync.aligned.m16n8k8.row.col.f32.tf32.tf32.f32 "
        "{%0,%1,%2,%3}, {%4,%5,%6,%7}, {%8,%9}, {%0,%1,%2,%3};"
        : "+f"(c[0]), "+f"(c[1]), "+f"(c[2]), "+f"(c[3])
        : "r"(a0), "r"(a1), "r"(a2), "r"(a3), "r"(b0), "r"(b1));
}
// fp16 m16n8k16 (S and PV), fp32 accumulate
__device__ __forceinline__ void mma16h(float* c,
    uint32_t a0, uint32_t a1, uint32_t a2, uint32_t a3,
    uint32_t b0, uint32_t b1)
{
    asm volatile(
        "mma.sync.aligned.m16n8k16.row.col.f32.f16.f16.f32 "
        "{%0,%1,%2,%3}, {%4,%5,%6,%7}, {%8,%9}, {%0,%1,%2,%3};"
        : "+f"(c[0]), "+f"(c[1]), "+f"(c[2]), "+f"(c[3])
        : "r"(a0), "r"(a1), "r"(a2), "r"(a3), "r"(b0), "r"(b1));
}
__device__ __forceinline__ void cp16(uint32_t dst, const void* src) {
    asm volatile("cp.async.cg.shared.global [%0], [%1], 16;" :: "r"(dst), "l"(src));
}
#define CP_COMMIT() asm volatile("cp.async.commit_group;" ::: "memory")
#define CP_WAIT1()  asm volatile("cp.async.wait_group 1;" ::: "memory")
#define CP_WAIT0()  asm volatile("cp.async.wait_group 0;" ::: "memory")

// ---------------------------------------------------------------------------
// Kernel 0: RoPE tables (double sincos of the fp32-rounded angle)
// ---------------------------------------------------------------------------
__global__ void rope_table_kernel() {
    int idx = blockIdx.x * blockDim.x + threadIdx.x;
    if (idx >= N_SEQ * 32) return;
    int n = idx >> 5, l = idx & 31;
    float invf = (float)exp(-((double)l / 32.0) * log(10000.0));
    float ang = (float)n * invf;
    double s, c;
    sincos((double)ang, &s, &c);
    g_cos[idx] = (float)c;
    g_sin[idx] = (float)s;
}

// ---------------------------------------------------------------------------
// Kernel 1: prep q/k: RoPE + l2norm + qk_scale (+0.125*log2e into q),
// packed fp16 layout [h][n][32w]. One warp per (token, head).
// ---------------------------------------------------------------------------
__global__ __launch_bounds__(256) void prep_qk_kernel(
    const float* __restrict__ q, const float* __restrict__ k,
    const float* __restrict__ qk_scale)
{
    int wi = blockIdx.x * 8 + (threadIdx.x >> 5);   // 0..65535
    int l = threadIdx.x & 31;
    int h = wi & 15;
    int n = wi >> 4;
    const float* src = (blockIdx.y == 0) ? q : k;
    uint32_t* dst = (blockIdx.y == 0) ? g_qf : g_kf;
    float fold = (blockIdx.y == 0) ? (0.125f * 1.4426950408889634f) : 1.0f;

    float2 x = ((const float2*)(src + (size_t)n * DIM + h * DIM_HEAD))[l];
    float2 sc = ((const float2*)qk_scale)[l];
    float c = g_cos[n * 32 + l], s = g_sin[n * 32 + l];
    float orr = x.x * c - x.y * s;
    float oii = x.x * s + x.y * c;
    float sq = orr * orr + oii * oii;
    #pragma unroll
    for (int m = 16; m; m >>= 1) sq += __shfl_xor_sync(0xffffffffu, sq, m);
    float f = fold / fmaxf(sqrtf(sq), 1e-12f);
    dst[((size_t)h * N_SEQ + n) * 32 + l] = packh2(orr * f * sc.x, oii * f * sc.y);
}

// ---------------------------------------------------------------------------
// Kernel 2a: v -> fp16 key-pair words g_vph[h][kp][d]
// thread handles one (h, kp, 4-dim chunk).
// ---------------------------------------------------------------------------
__global__ __launch_bounds__(256) void vpair_kernel(const float* __restrict__ v) {
    int id = blockIdx.x * 256 + threadIdx.x;       // 0 .. 524287
    int h = id >> 15;
    int rem = id & 32767;
    int kp = rem >> 4;                              // 0..2047 (keys 2kp, 2kp+1)
    int chunk = rem & 15;
    float4 a = *(const float4*)(v + (size_t)(2 * kp) * DIM + h * 64 + chunk * 4);
    float4 b = *(const float4*)(v + (size_t)(2 * kp + 1) * DIM + h * 64 + chunk * 4);
    uint32_t* dst = g_vph + (((size_t)h * 2048 + kp) * 64 + chunk * 4);
    dst[0] = packh2(a.x, b.x);
    dst[1] = packh2(a.y, b.y);
    dst[2] = packh2(a.z, b.z);
    dst[3] = packh2(a.w, b.w);
}

// ---------------------------------------------------------------------------
// Kernel 2b: elementwise rna rounding of w_out (tf32 operand for proj)
// ---------------------------------------------------------------------------
__global__ __launch_bounds__(256) void wround_kernel(const float* __restrict__ w) {
    int i = blockIdx.x * 256 + threadIdx.x;
    float4 x = ((const float4*)w)[i];
    ((float4*)g_wr)[i] = make_float4(tf32_rna(x.x), tf32_rna(x.y), tf32_rna(x.z), tf32_rna(x.w));
}

// ---------------------------------------------------------------------------
// Kernel 3: flash attention, all-fp16 MMA. CTA = 128 q-rows x 1 head;
// 8 warps x 16 rows; 64 KV tiles of 64 keys, double-buffered cp.async.
// S: single-pass fp16 m16n8k16 (32 MMA/tile/warp). PV: fp16 m16n8k16
// (32 MMA) — S C-frags pack DIRECTLY into PV A-frags (no shuffles).
// Fixed-max softmax (CMAX), O accumulated fp32 across tiles.
// SMEM per buffer: K 64 rows x 36 words (9216B) + Vp 32 kp x 72 words
// (9216B) = 18432B; two buffers = 36864B.
// ---------------------------------------------------------------------------
#define V_OFF 9216
#define KV_STR_B 18432
#define ATTN_SMEM_BYTES (2 * KV_STR_B)

__device__ __forceinline__ void issue_kv(uint32_t base, int h, int k0, int tid)
{
    #pragma unroll
    for (int j = 0; j < 2; j++) {
        int id = tid + j * 256;       // 0..511
        int row = id >> 3;            // 0..63
        int ch = id & 7;              // 16B chunk
        cp16(base + (uint32_t)(row * 144 + ch * 16),
             g_kf + ((size_t)h * N_SEQ + k0 + row) * 32 + ch * 4);
    }
    int kp0 = k0 >> 1;
    #pragma unroll
    for (int j = 0; j < 2; j++) {
        int id = tid + j * 256;       // 0..511
        int row = id >> 4;            // kp row 0..31
        int ch = id & 15;             // 16B chunk
        cp16(base + (uint32_t)(V_OFF + row * 288 + ch * 16),
             g_vph + ((size_t)h * 2048 + kp0 + row) * 64 + ch * 4);
    }
}

__global__ __launch_bounds__(256) void attn_kernel()
{
    extern __shared__ char smb[];
    uint32_t kvu0 = smem_u32(smb);

    int tid = threadIdx.x;
    int warp = tid >> 5, lane = tid & 31;
    int r = lane >> 2, c = lane & 3;
    int h = blockIdx.y, m0 = blockIdx.x * 128;

    issue_kv(kvu0, h, 0, tid);             CP_COMMIT();
    issue_kv(kvu0 + KV_STR_B, h, 64, tid); CP_COMMIT();

    // Q fragments, tile-invariant: 4 k16-steps x 4 regs
    uint32_t qf[4][4];
    {
        const uint32_t* qp = g_qf + ((size_t)h * N_SEQ + m0 + warp * 16 + r) * 32;
        #pragma unroll
        for (int ks = 0; ks < 4; ks++) {
            qf[ks][0] = qp[ks * 8 + c];
            qf[ks][1] = qp[256 + ks * 8 + c];
            qf[ks][2] = qp[ks * 8 + c + 4];
            qf[ks][3] = qp[256 + ks * 8 + c + 4];
        }
    }

    float s[8][4], o[8][4];
    float lsum0 = 0.0f, lsum1 = 0.0f;
    #pragma unroll
    for (int nf = 0; nf < 8; nf++)
        #pragma unroll
        for (int e = 0; e < 4; e++) o[nf][e] = 0.0f;

    for (int t = 0; t < 64; t++) {
        if (t == 63) { CP_WAIT0(); } else { CP_WAIT1(); }
        __syncthreads();
        const uint32_t* KW = (const uint32_t*)(smb + (t & 1) * KV_STR_B);
        const uint32_t* Vw = (const uint32_t*)(smb + (t & 1) * KV_STR_B + V_OFF);

        #pragma unroll
        for (int nf = 0; nf < 8; nf++)
            #pragma unroll
            for (int e = 0; e < 4; e++) s[nf][e] = 0.0f;

        // ---- S = Q K^T, single-pass fp16 k16 ----
        #pragma unroll
        for (int nf = 0; nf < 8; nf++) {
            const uint32_t* kb = KW + (nf * 8 + r) * 36 + c;
            #pragma unroll
            for (int ks = 0; ks < 4; ks++) {
                mma16h(s[nf], qf[ks][0], qf[ks][1], qf[ks][2], qf[ks][3],
                       kb[ks * 8], kb[ks * 8 + 4]);
            }
        }

        // ---- softmax numerators (log2 units, fixed shift) ----
        #pragma unroll
        for (int nf = 0; nf < 8; nf++) {
            s[nf][0] = exp2f(s[nf][0] - CMAX);
            s[nf][1] = exp2f(s[nf][1] - CMAX);
            s[nf][2] = exp2f(s[nf][2] - CMAX);
            s[nf][3] = exp2f(s[nf][3] - CMAX);
            lsum0 += s[nf][0] + s[nf][1];
            lsum1 += s[nf][2] + s[nf][3];
        }

        // ---- O += P V (fp16 k16): S C-frags pack DIRECTLY into A-frags ----
        #pragma unroll
        for (int k2 = 0; k2 < 4; k2++) {
            uint32_t a0 = packh2(s[2 * k2][0],     s[2 * k2][1]);
            uint32_t a1 = packh2(s[2 * k2][2],     s[2 * k2][3]);
            uint32_t a2 = packh2(s[2 * k2 + 1][0], s[2 * k2 + 1][1]);
            uint32_t a3 = packh2(s[2 * k2 + 1][2], s[2 * k2 + 1][3]);
            const uint32_t* vb = Vw + (k2 * 8 + c) * 72 + r;
            #pragma unroll
            for (int nf = 0; nf < 8; nf++) {
                mma16h(o[nf], a0, a1, a2, a3, vb[nf * 8], vb[4 * 72 + nf * 8]);
            }
        }

        __syncthreads();
        if (t + 2 < 64) {
            issue_kv(kvu0 + (uint32_t)(t & 1) * KV_STR_B, h, (t + 2) * 64, tid);
            CP_COMMIT();
        }
    }

    // ---- epilogue: quad row sums, normalize, rna, store ----
    lsum0 += __shfl_xor_sync(0xffffffffu, lsum0, 1);
    lsum0 += __shfl_xor_sync(0xffffffffu, lsum0, 2);
    lsum1 += __shfl_xor_sync(0xffffffffu, lsum1, 1);
    lsum1 += __shfl_xor_sync(0xffffffffu, lsum1, 2);
    float inv0 = 1.0f / lsum0, inv1 = 1.0f / lsum1;
    int row0 = m0 + warp * 16 + r;
    #pragma unroll
    for (int nf = 0; nf < 8; nf++) {
        int col = h * DIM_HEAD + nf * 8 + 2 * c;
        float2 x0 = make_float2(tf32_rna(o[nf][0] * inv0), tf32_rna(o[nf][1] * inv0));
        float2 x1 = make_float2(tf32_rna(o[nf][2] * inv1), tf32_rna(o[nf][3] * inv1));
        *(float2*)&g_attn[(size_t)row0 * DIM + col] = x0;
        *(float2*)&g_attn[(size_t)(row0 + 8) * DIM + col] = x1;
    }
}

// ---------------------------------------------------------------------------
// Kernel 4: projection GEMM on mma.sync tf32 (unchanged, validated R5/R8).
// out[n][j] = sum_i attn[n][i] * w[j][i] + b[j]. CTA 128x128, warps 4x2.
// ---------------------------------------------------------------------------
#define PROJ_STRF 17408
#define PROJ_SMEM_BYTES (2 * PROJ_STRF * 4)

__device__ __forceinline__ void issue_proj(uint32_t base, int m0, int j0, int k0, int tid)
{
    #pragma unroll
    for (int j = 0; j < 8; j++) {
        int id = tid + j * 256;
        int row = id >> 4;
        int c4 = (id & 15) * 4;
        cp16(base + (uint32_t)(row * 68 + c4) * 4u,
             g_attn + (size_t)(m0 + row) * DIM + k0 + c4);
        cp16(base + (uint32_t)(8704 + row * 68 + c4) * 4u,
             g_wr + (size_t)(j0 + row) * DIM + k0 + c4);
    }
}

__global__ __launch_bounds__(256) void proj_kernel(
    const float* __restrict__ b_out, float* __restrict__ out)
{
    extern __shared__ float sm[];
    uint32_t smu = smem_u32(sm);
    int tid = threadIdx.x;
    int warp = tid >> 5, lane = tid & 31;
    int r = lane >> 2, c = lane & 3;
    int mw = warp >> 1, nw = warp & 1;
    int m0 = blockIdx.x * 128, j0 = blockIdx.y * 128;

    float acc[2][8][4];
    #pragma unroll
    for (int mf = 0; mf < 2; mf++)
        #pragma unroll
        for (int nf = 0; nf < 8; nf++)
            #pragma unroll
            for (int e = 0; e < 4; e++) acc[mf][nf][e] = 0.0f;

    issue_proj(smu, m0, j0, 0, tid);                    CP_COMMIT();
    issue_proj(smu + PROJ_STRF * 4u, m0, j0, 64, tid);  CP_COMMIT();

    for (int ch = 0; ch < 16; ch++) {
        if (ch == 15) { CP_WAIT0(); } else { CP_WAIT1(); }
        __syncthreads();
        float* As = sm + (ch & 1) * PROJ_STRF;
        float* Ws = As + 8704;

        #pragma unroll
        for (int ks = 0; ks < 8; ks++) {
            int k0 = ks * 8;
            uint32_t a[2][4];
            #pragma unroll
            for (int mf = 0; mf < 2; mf++) {
                const float* ab = &As[(mw * 32 + mf * 16 + r) * 68 + k0 + c];
                a[mf][0] = __float_as_uint(ab[0]);
                a[mf][1] = __float_as_uint(ab[8 * 68]);
                a[mf][2] = __float_as_uint(ab[4]);
                a[mf][3] = __float_as_uint(ab[8 * 68 + 4]);
            }
            #pragma unroll
            for (int nf = 0; nf < 8; nf++) {
                const float* wb = &Ws[(nw * 64 + nf * 8 + r) * 68 + k0 + c];
                uint32_t b0 = __float_as_uint(wb[0]);
                uint32_t b1 = __float_as_uint(wb[4]);
                mma8(acc[0][nf], a[0][0], a[0][1], a[0][2], a[0][3], b0, b1);
                mma8(acc[1][nf], a[1][0], a[1][1], a[1][2], a[1][3], b0, b1);
            }
        }

        __syncthreads();
        if (ch + 2 < 16) {
            issue_proj(smu + (uint32_t)(ch & 1) * PROJ_STRF * 4u, m0, j0, (ch + 2) * 64, tid);
            CP_COMMIT();
        }
    }

    #pragma unroll
    for (int mf = 0; mf < 2; mf++) {
        int row = m0 + mw * 32 + mf * 16 + r;
        #pragma unroll
        for (int nf = 0; nf < 8; nf++) {
            int col = j0 + nw * 64 + nf * 8 + 2 * c;
            float2 bb = *(const float2*)&b_out[col];
            *(float2*)&out[(size_t)row * DIM + col] =
                make_float2(acc[mf][nf][0] + bb.x, acc[mf][nf][1] + bb.y);
            *(float2*)&out[(size_t)(row + 8) * DIM + col] =
                make_float2(acc[mf][nf][2] + bb.x, acc[mf][nf][3] + bb.y);
        }
    }
}

// ---------------------------------------------------------------------------
extern "C" void kernel_launch(void* const* d_in, const int* in_sizes, int n_in,
                              void* d_out, int out_size)
{
    const float* q        = (const float*)d_in[0];
    const float* k        = (const float*)d_in[1];
    const float* v        = (const float*)d_in[2];
    const float* qk_scale = (const float*)d_in[3];
    const float* w_out    = (const float*)d_in[4];
    const float* b_out    = (const float*)d_in[5];
    float* out = (float*)d_out;

    cudaFuncSetAttribute(attn_kernel,
                         cudaFuncAttributeMaxDynamicSharedMemorySize, ATTN_SMEM_BYTES);
    cudaFuncSetAttribute(proj_kernel,
                         cudaFuncAttributeMaxDynamicSharedMemorySize, PROJ_SMEM_BYTES);

    rope_table_kernel<<<(N_SEQ * 32 + 255) / 256, 256>>>();
    prep_qk_kernel<<<dim3(8192, 2), 256>>>(q, k, qk_scale);
    vpair_kernel<<<2048, 256>>>(v);
    wround_kernel<<<(DIM * DIM / 4) / 256, 256>>>(w_out);
    attn_kernel<<<dim3(N_SEQ / 128, N_HEADS), 256, ATTN_SMEM_BYTES>>>();
    proj_kernel<<<dim3(N_SEQ / 128, DIM / 128), 256, PROJ_SMEM_BYTES>>>(b_out, out);
}

// round 16
// speedup vs baseline: 2.3246x; 1.1394x over previous
#include <cuda_runtime.h>
#include <cuda_bf16.h>
#include <cuda_fp16.h>
#include <math.h>
#include <stdint.h>

#define N_SEQ 4096
#define N_HEADS 16
#define DIM_HEAD 64
#define DIM 1024
#define CMAX 18.5f

// ---------------- scratch (device globals; no allocation allowed) ----------
// q/k after rope+l2norm+qk_scale (+0.125*log2e folded into q), packed fp16
// pairs: word w = dims (2w, 2w+1). Layout [h][n][32 words].
__device__ uint32_t g_qf[N_HEADS * N_SEQ * 32];
__device__ uint32_t g_kf[N_HEADS * N_SEQ * 32];
// v as fp16 KEY-PAIR words for the m16n8k16 B-fragment:
// g_vph[h][kp][d] = {V[2kp][d] (lo), V[2kp+1][d] (hi)}, kp = 0..2047, d = 0..63
__device__ uint32_t g_vph[N_HEADS * 2048 * 64];
__device__ float g_wr [DIM * DIM];                   // w_out, tf32-rna, natural [j][i]
__device__ float g_attn[N_SEQ * DIM];                // attention out, tf32-rna, [n][dim]
__device__ float g_cos[N_SEQ * 32];
__device__ float g_sin[N_SEQ * 32];

// ---------------- helpers ---------------------------------------------------
__device__ __forceinline__ uint32_t smem_u32(const void* p) {
    uint32_t a;
    asm("{ .reg .u64 t; cvta.to.shared.u64 t, %1; cvt.u32.u64 %0, t; }" : "=r"(a) : "l"(p));
    return a;
}
__device__ __forceinline__ float tf32_rna(float x) {
    uint32_t r;
    asm("cvt.rna.tf32.f32 %0, %1;" : "=r"(r) : "f"(x));
    return __uint_as_float(r);
}
__device__ __forceinline__ float ex2(float x) {
    float r;
    asm("ex2.approx.ftz.f32 %0, %1;" : "=f"(r) : "f"(x));
    return r;
}
__device__ __forceinline__ uint32_t packh2(float a, float b) {
    __half2 t = __floats2half2_rn(a, b);   // a -> low half (lower index)
    return *(uint32_t*)&t;
}
// tf32 m16n8k8 (projection)
__device__ __forceinline__ void mma8(float* c,
    uint32_t a0, uint32_t a1, uint32_t a2, uint32_t a3,
    uint32_t b0, uint32_t b1)
{
    asm volatile(
        "mma.sync.aligned.m16n8k8.row.col.f32.tf32.tf32.f32 "
        "{%0,%1,%2,%3}, {%4,%5,%6,%7}, {%8,%9}, {%0,%1,%2,%3};"
        : "+f"(c[0]), "+f"(c[1]), "+f"(c[2]), "+f"(c[3])
        : "r"(a0), "r"(a1), "r"(a2), "r"(a3), "r"(b0), "r"(b1));
}
// fp16 m16n8k16 (S and PV), fp32 accumulate
__device__ __forceinline__ void mma16h(float* c,
    uint32_t a0, uint32_t a1, uint32_t a2, uint32_t a3,
    uint32_t b0, uint32_t b1)
{
    asm volatile(
        "mma.sync.aligned.m16n8k16.row.col.f32.f16.f16.f32 "
        "{%0,%1,%2,%3}, {%4,%5,%6,%7}, {%8,%9}, {%0,%1,%2,%3};"
        : "+f"(c[0]), "+f"(c[1]), "+f"(c[2]), "+f"(c[3])
        : "r"(a0), "r"(a1), "r"(a2), "r"(a3), "r"(b0), "r"(b1));
}
__device__ __forceinline__ void cp16(uint32_t dst, const void* src) {
    asm volatile("cp.async.cg.shared.global [%0], [%1], 16;" :: "r"(dst), "l"(src));
}
#define CP_COMMIT() asm volatile("cp.async.commit_group;" ::: "memory")
#define CP_WAIT1()  asm volatile("cp.async.wait_group 1;" ::: "memory")
#define CP_WAIT0()  asm volatile("cp.async.wait_group 0;" ::: "memory")

// ---------------------------------------------------------------------------
// Kernel 0: RoPE tables (double sincos of the fp32-rounded angle)
// ---------------------------------------------------------------------------
__global__ void rope_table_kernel() {
    int idx = blockIdx.x * blockDim.x + threadIdx.x;
    if (idx >= N_SEQ * 32) return;
    int n = idx >> 5, l = idx & 31;
    float invf = (float)exp(-((double)l / 32.0) * log(10000.0));
    float ang = (float)n * invf;
    double s, c;
    sincos((double)ang, &s, &c);
    g_cos[idx] = (float)c;
    g_sin[idx] = (float)s;
}

// ---------------------------------------------------------------------------
// Kernel 1: prep q/k: RoPE + l2norm + qk_scale (+0.125*log2e into q),
// packed fp16 layout [h][n][32w]. One warp per (token, head).
// ---------------------------------------------------------------------------
__global__ __launch_bounds__(256) void prep_qk_kernel(
    const float* __restrict__ q, const float* __restrict__ k,
    const float* __restrict__ qk_scale)
{
    int wi = blockIdx.x * 8 + (threadIdx.x >> 5);   // 0..65535
    int l = threadIdx.x & 31;
    int h = wi & 15;
    int n = wi >> 4;
    const float* src = (blockIdx.y == 0) ? q : k;
    uint32_t* dst = (blockIdx.y == 0) ? g_qf : g_kf;
    float fold = (blockIdx.y == 0) ? (0.125f * 1.4426950408889634f) : 1.0f;

    float2 x = ((const float2*)(src + (size_t)n * DIM + h * DIM_HEAD))[l];
    float2 sc = ((const float2*)qk_scale)[l];
    float c = g_cos[n * 32 + l], s = g_sin[n * 32 + l];
    float orr = x.x * c - x.y * s;
    float oii = x.x * s + x.y * c;
    float sq = orr * orr + oii * oii;
    #pragma unroll
    for (int m = 16; m; m >>= 1) sq += __shfl_xor_sync(0xffffffffu, sq, m);
    float f = fold / fmaxf(sqrtf(sq), 1e-12f);
    dst[((size_t)h * N_SEQ + n) * 32 + l] = packh2(orr * f * sc.x, oii * f * sc.y);
}

// ---------------------------------------------------------------------------
// Kernel 2a: v -> fp16 key-pair words g_vph[h][kp][d]
// thread handles one (h, kp, 4-dim chunk).
// ---------------------------------------------------------------------------
__global__ __launch_bounds__(256) void vpair_kernel(const float* __restrict__ v) {
    int id = blockIdx.x * 256 + threadIdx.x;       // 0 .. 524287
    int h = id >> 15;
    int rem = id & 32767;
    int kp = rem >> 4;                              // 0..2047 (keys 2kp, 2kp+1)
    int chunk = rem & 15;
    float4 a = *(const float4*)(v + (size_t)(2 * kp) * DIM + h * 64 + chunk * 4);
    float4 b = *(const float4*)(v + (size_t)(2 * kp + 1) * DIM + h * 64 + chunk * 4);
    uint32_t* dst = g_vph + (((size_t)h * 2048 + kp) * 64 + chunk * 4);
    dst[0] = packh2(a.x, b.x);
    dst[1] = packh2(a.y, b.y);
    dst[2] = packh2(a.z, b.z);
    dst[3] = packh2(a.w, b.w);
}

// ---------------------------------------------------------------------------
// Kernel 2b: elementwise rna rounding of w_out (tf32 operand for proj)
// ---------------------------------------------------------------------------
__global__ __launch_bounds__(256) void wround_kernel(const float* __restrict__ w) {
    int i = blockIdx.x * 256 + threadIdx.x;
    float4 x = ((const float4*)w)[i];
    ((float4*)g_wr)[i] = make_float4(tf32_rna(x.x), tf32_rna(x.y), tf32_rna(x.z), tf32_rna(x.w));
}

// ---------------------------------------------------------------------------
// Kernel 3: flash attention, all-fp16 MMA. CTA = 128 q-rows x 1 head;
// 8 warps x 16 rows; 64 KV tiles of 64 keys, double-buffered cp.async.
// S: single-pass fp16 m16n8k16 (32 MMA/tile/warp). PV: fp16 m16n8k16
// (32 MMA) — S C-frags pack DIRECTLY into PV A-frags (no shuffles).
// Fixed-max softmax (CMAX), O accumulated fp32 across tiles.
// SMEM per buffer: K 64x36w (9216B) + Vp 32x72w (9216B) = 18432B;
// two buffers = 36864B. __launch_bounds__(256,2): 2 CTAs/SM so one CTA's
// MUFU-heavy softmax overlaps the other's MMA-heavy S/PV phases.
// ---------------------------------------------------------------------------
#define V_OFF 9216
#define KV_STR_B 18432
#define ATTN_SMEM_BYTES (2 * KV_STR_B)

__device__ __forceinline__ void issue_kv(uint32_t base, int h, int k0, int tid)
{
    #pragma unroll
    for (int j = 0; j < 2; j++) {
        int id = tid + j * 256;       // 0..511
        int row = id >> 3;            // 0..63
        int ch = id & 7;              // 16B chunk
        cp16(base + (uint32_t)(row * 144 + ch * 16),
             g_kf + ((size_t)h * N_SEQ + k0 + row) * 32 + ch * 4);
    }
    int kp0 = k0 >> 1;
    #pragma unroll
    for (int j = 0; j < 2; j++) {
        int id = tid + j * 256;       // 0..511
        int row = id >> 4;            // kp row 0..31
        int ch = id & 15;             // 16B chunk
        cp16(base + (uint32_t)(V_OFF + row * 288 + ch * 16),
             g_vph + ((size_t)h * 2048 + kp0 + row) * 64 + ch * 4);
    }
}

__global__ __launch_bounds__(256, 2) void attn_kernel()
{
    extern __shared__ char smb[];
    uint32_t kvu0 = smem_u32(smb);

    int tid = threadIdx.x;
    int warp = tid >> 5, lane = tid & 31;
    int r = lane >> 2, c = lane & 3;
    int h = blockIdx.y, m0 = blockIdx.x * 128;

    issue_kv(kvu0, h, 0, tid);             CP_COMMIT();
    issue_kv(kvu0 + KV_STR_B, h, 64, tid); CP_COMMIT();

    // Q fragments, tile-invariant: 4 k16-steps x 4 regs
    uint32_t qf[4][4];
    {
        const uint32_t* qp = g_qf + ((size_t)h * N_SEQ + m0 + warp * 16 + r) * 32;
        #pragma unroll
        for (int ks = 0; ks < 4; ks++) {
            qf[ks][0] = qp[ks * 8 + c];
            qf[ks][1] = qp[256 + ks * 8 + c];
            qf[ks][2] = qp[ks * 8 + c + 4];
            qf[ks][3] = qp[256 + ks * 8 + c + 4];
        }
    }

    float s[8][4], o[8][4];
    float lsum0 = 0.0f, lsum1 = 0.0f;
    #pragma unroll
    for (int nf = 0; nf < 8; nf++)
        #pragma unroll
        for (int e = 0; e < 4; e++) o[nf][e] = 0.0f;

    for (int t = 0; t < 64; t++) {
        if (t == 63) { CP_WAIT0(); } else { CP_WAIT1(); }
        __syncthreads();
        const uint32_t* KW = (const uint32_t*)(smb + (t & 1) * KV_STR_B);
        const uint32_t* Vw = (const uint32_t*)(smb + (t & 1) * KV_STR_B + V_OFF);

        #pragma unroll
        for (int nf = 0; nf < 8; nf++)
            #pragma unroll
            for (int e = 0; e < 4; e++) s[nf][e] = 0.0f;

        // ---- S = Q K^T, single-pass fp16 k16 ----
        #pragma unroll
        for (int nf = 0; nf < 8; nf++) {
            const uint32_t* kb = KW + (nf * 8 + r) * 36 + c;
            #pragma unroll
            for (int ks = 0; ks < 4; ks++) {
                mma16h(s[nf], qf[ks][0], qf[ks][1], qf[ks][2], qf[ks][3],
                       kb[ks * 8], kb[ks * 8 + 4]);
            }
        }

        // ---- softmax numerators (log2 units, fixed shift) ----
        #pragma unroll
        for (int nf = 0; nf < 8; nf++) {
            s[nf][0] = ex2(s[nf][0] - CMAX);
            s[nf][1] = ex2(s[nf][1] - CMAX);
            s[nf][2] = ex2(s[nf][2] - CMAX);
            s[nf][3] = ex2(s[nf][3] - CMAX);
            lsum0 += s[nf][0] + s[nf][1];
            lsum1 += s[nf][2] + s[nf][3];
        }

        // ---- O += P V (fp16 k16): S C-frags pack DIRECTLY into A-frags ----
        #pragma unroll
        for (int k2 = 0; k2 < 4; k2++) {
            uint32_t a0 = packh2(s[2 * k2][0],     s[2 * k2][1]);
            uint32_t a1 = packh2(s[2 * k2][2],     s[2 * k2][3]);
            uint32_t a2 = packh2(s[2 * k2 + 1][0], s[2 * k2 + 1][1]);
            uint32_t a3 = packh2(s[2 * k2 + 1][2], s[2 * k2 + 1][3]);
            const uint32_t* vb = Vw + (k2 * 8 + c) * 72 + r;
            #pragma unroll
            for (int nf = 0; nf < 8; nf++) {
                mma16h(o[nf], a0, a1, a2, a3, vb[nf * 8], vb[4 * 72 + nf * 8]);
            }
        }

        __syncthreads();
        if (t + 2 < 64) {
            issue_kv(kvu0 + (uint32_t)(t & 1) * KV_STR_B, h, (t + 2) * 64, tid);
            CP_COMMIT();
        }
    }

    // ---- epilogue: quad row sums, normalize, rna, store ----
    lsum0 += __shfl_xor_sync(0xffffffffu, lsum0, 1);
    lsum0 += __shfl_xor_sync(0xffffffffu, lsum0, 2);
    lsum1 += __shfl_xor_sync(0xffffffffu, lsum1, 1);
    lsum1 += __shfl_xor_sync(0xffffffffu, lsum1, 2);
    float inv0 = 1.0f / lsum0, inv1 = 1.0f / lsum1;
    int row0 = m0 + warp * 16 + r;
    #pragma unroll
    for (int nf = 0; nf < 8; nf++) {
        int col = h * DIM_HEAD + nf * 8 + 2 * c;
        float2 x0 = make_float2(tf32_rna(o[nf][0] * inv0), tf32_rna(o[nf][1] * inv0));
        float2 x1 = make_float2(tf32_rna(o[nf][2] * inv1), tf32_rna(o[nf][3] * inv1));
        *(float2*)&g_attn[(size_t)row0 * DIM + col] = x0;
        *(float2*)&g_attn[(size_t)(row0 + 8) * DIM + col] = x1;
    }
}

// ---------------------------------------------------------------------------
// Kernel 4: projection GEMM on mma.sync tf32 (unchanged, validated R5/R8).
// out[n][j] = sum_i attn[n][i] * w[j][i] + b[j]. CTA 128x128, warps 4x2.
// ---------------------------------------------------------------------------
#define PROJ_STRF 17408
#define PROJ_SMEM_BYTES (2 * PROJ_STRF * 4)

__device__ __forceinline__ void issue_proj(uint32_t base, int m0, int j0, int k0, int tid)
{
    #pragma unroll
    for (int j = 0; j < 8; j++) {
        int id = tid + j * 256;
        int row = id >> 4;
        int c4 = (id & 15) * 4;
        cp16(base + (uint32_t)(row * 68 + c4) * 4u,
             g_attn + (size_t)(m0 + row) * DIM + k0 + c4);
        cp16(base + (uint32_t)(8704 + row * 68 + c4) * 4u,
             g_wr + (size_t)(j0 + row) * DIM + k0 + c4);
    }
}

__global__ __launch_bounds__(256) void proj_kernel(
    const float* __restrict__ b_out, float* __restrict__ out)
{
    extern __shared__ float sm[];
    uint32_t smu = smem_u32(sm);
    int tid = threadIdx.x;
    int warp = tid >> 5, lane = tid & 31;
    int r = lane >> 2, c = lane & 3;
    int mw = warp >> 1, nw = warp & 1;
    int m0 = blockIdx.x * 128, j0 = blockIdx.y * 128;

    float acc[2][8][4];
    #pragma unroll
    for (int mf = 0; mf < 2; mf++)
        #pragma unroll
        for (int nf = 0; nf < 8; nf++)
            #pragma unroll
            for (int e = 0; e < 4; e++) acc[mf][nf][e] = 0.0f;

    issue_proj(smu, m0, j0, 0, tid);                    CP_COMMIT();
    issue_proj(smu + PROJ_STRF * 4u, m0, j0, 64, tid);  CP_COMMIT();

    for (int ch = 0; ch < 16; ch++) {
        if (ch == 15) { CP_WAIT0(); } else { CP_WAIT1(); }
        __syncthreads();
        float* As = sm + (ch & 1) * PROJ_STRF;
        float* Ws = As + 8704;

        #pragma unroll
        for (int ks = 0; ks < 8; ks++) {
            int k0 = ks * 8;
            uint32_t a[2][4];
            #pragma unroll
            for (int mf = 0; mf < 2; mf++) {
                const float* ab = &As[(mw * 32 + mf * 16 + r) * 68 + k0 + c];
                a[mf][0] = __float_as_uint(ab[0]);
                a[mf][1] = __float_as_uint(ab[8 * 68]);
                a[mf][2] = __float_as_uint(ab[4]);
                a[mf][3] = __float_as_uint(ab[8 * 68 + 4]);
            }
            #pragma unroll
            for (int nf = 0; nf < 8; nf++) {
                const float* wb = &Ws[(nw * 64 + nf * 8 + r) * 68 + k0 + c];
                uint32_t b0 = __float_as_uint(wb[0]);
                uint32_t b1 = __float_as_uint(wb[4]);
                mma8(acc[0][nf], a[0][0], a[0][1], a[0][2], a[0][3], b0, b1);
                mma8(acc[1][nf], a[1][0], a[1][1], a[1][2], a[1][3], b0, b1);
            }
        }

        __syncthreads();
        if (ch + 2 < 16) {
            issue_proj(smu + (uint32_t)(ch & 1) * PROJ_STRF * 4u, m0, j0, (ch + 2) * 64, tid);
            CP_COMMIT();
        }
    }

    #pragma unroll
    for (int mf = 0; mf < 2; mf++) {
        int row = m0 + mw * 32 + mf * 16 + r;
        #pragma unroll
        for (int nf = 0; nf < 8; nf++) {
            int col = j0 + nw * 64 + nf * 8 + 2 * c;
            float2 bb = *(const float2*)&b_out[col];
            *(float2*)&out[(size_t)row * DIM + col] =
                make_float2(acc[mf][nf][0] + bb.x, acc[mf][nf][1] + bb.y);
            *(float2*)&out[(size_t)(row + 8) * DIM + col] =
                make_float2(acc[mf][nf][2] + bb.x, acc[mf][nf][3] + bb.y);
        }
    }
}

// ---------------------------------------------------------------------------
extern "C" void kernel_launch(void* const* d_in, const int* in_sizes, int n_in,
                              void* d_out, int out_size)
{
    const float* q        = (const float*)d_in[0];
    const float* k        = (const float*)d_in[1];
    const float* v        = (const float*)d_in[2];
    const float* qk_scale = (const float*)d_in[3];
    const float* w_out    = (const float*)d_in[4];
    const float* b_out    = (const float*)d_in[5];
    float* out = (float*)d_out;

    cudaFuncSetAttribute(attn_kernel,
                         cudaFuncAttributeMaxDynamicSharedMemorySize, ATTN_SMEM_BYTES);
    cudaFuncSetAttribute(proj_kernel,
                         cudaFuncAttributeMaxDynamicSharedMemorySize, PROJ_SMEM_BYTES);

    rope_table_kernel<<<(N_SEQ * 32 + 255) / 256, 256>>>();
    prep_qk_kernel<<<dim3(8192, 2), 256>>>(q, k, qk_scale);
    vpair_kernel<<<2048, 256>>>(v);
    wround_kernel<<<(DIM * DIM / 4) / 256, 256>>>(w_out);
    attn_kernel<<<dim3(N_SEQ / 128, N_HEADS), 256, ATTN_SMEM_BYTES>>>();
    proj_kernel<<<dim3(N_SEQ / 128, DIM / 128), 256, PROJ_SMEM_BYTES>>>(b_out, out);
}